// round 15
// baseline (speedup 1.0000x reference)
#include <cuda_runtime.h>
#include <cuda_bf16.h>

typedef unsigned u32; typedef unsigned long long u64;
#define BB 64
#define SS 4096
#define DD 64
#define FF 256
#define INV_SIGMA 0.3535533905932738f
#define LOG2E 1.4426950408889634f

__device__ float g_mean[BB * DD];
__device__ float g_kvT [BB * DD * FF];   // [b][d][f]
__device__ float g_ksum[BB * FF];
__device__ unsigned g_bar;

// ---------------- helpers ----------------------------------------------------
__device__ __forceinline__ u32 smem_u32(const void* p) {
    u32 a; asm("{ .reg .u64 t; cvta.to.shared.u64 t, %1; cvt.u32.u64 %0, t; }" : "=r"(a) : "l"(p));
    return a;
}
__device__ __forceinline__ void sts32(u32 a, u32 v) {
    asm volatile("st.shared.b32 [%0], %1;" :: "r"(a), "r"(v) : "memory");
}
__device__ __forceinline__ float ex2f(float x) {
    float r; asm("ex2.approx.ftz.f32 %0, %1;" : "=f"(r) : "f"(x)); return r;
}
__device__ __forceinline__ void split2(float a, float b, u32& hi, u32& lo) {
    u32 h; asm("cvt.rn.bf16x2.f32 %0,%1,%2;" : "=r"(h) : "f"(b), "f"(a));
    float ah = __uint_as_float(h << 16), bh = __uint_as_float(h & 0xffff0000u);
    float ar = a - ah, br = b - bh;
    asm("cvt.rn.bf16x2.f32 %0,%1,%2;" : "=r"(lo) : "f"(br), "f"(ar));
    hi = h;
}
__device__ __forceinline__ void ldsm4(u32 a, u32& r0, u32& r1, u32& r2, u32& r3) {
    asm volatile("ldmatrix.sync.aligned.m8n8.x4.shared.b16 {%0,%1,%2,%3}, [%4];"
                 : "=r"(r0), "=r"(r1), "=r"(r2), "=r"(r3) : "r"(a));
}
__device__ __forceinline__ void ldsm4t(u32 a, u32& r0, u32& r1, u32& r2, u32& r3) {
    asm volatile("ldmatrix.sync.aligned.m8n8.x4.trans.shared.b16 {%0,%1,%2,%3}, [%4];"
                 : "=r"(r0), "=r"(r1), "=r"(r2), "=r"(r3) : "r"(a));
}
__device__ __forceinline__ void ldsm2t(u32 a, u32& r0, u32& r1) {
    asm volatile("ldmatrix.sync.aligned.m8n8.x2.trans.shared.b16 {%0,%1}, [%2];"
                 : "=r"(r0), "=r"(r1) : "r"(a));
}
__device__ __forceinline__ void mma16816(float* c, u32 a0, u32 a1, u32 a2, u32 a3, u32 b0, u32 b1) {
    asm volatile("mma.sync.aligned.m16n8k16.row.col.f32.bf16.bf16.f32 "
                 "{%0,%1,%2,%3},{%4,%5,%6,%7},{%8,%9},{%0,%1,%2,%3};"
                 : "+f"(c[0]), "+f"(c[1]), "+f"(c[2]), "+f"(c[3])
                 : "r"(a0), "r"(a1), "r"(a2), "r"(a3), "r"(b0), "r"(b1));
}

// stage HALF of a 64-float row (h = 0/1) as bf16 hi(/lo) into pitch-144B tile
__device__ __forceinline__ void stage_half(u32 hB, u32 lB, const float4* row, int r, int h,
                                           float scale, const float* cen, float* nsq_part) {
    const u32 rb = (u32)r * 144u + (u32)h * 64u;
    float nsq = 0.0f;
#pragma unroll
    for (int i = 0; i < 8; i++) {
        float4 x = row[h * 8 + i];
        float c0 = x.x * scale, c1 = x.y * scale, c2 = x.z * scale, c3 = x.w * scale;
        if (cen) {
            const float* cc = cen + h * 32 + 4 * i;
            c0 -= cc[0]; c1 -= cc[1]; c2 -= cc[2]; c3 -= cc[3];
        }
        if (nsq_part) nsq += c0*c0 + c1*c1 + c2*c2 + c3*c3;
        u32 h0, l0, h1, l1;
        split2(c0, c1, h0, l0); split2(c2, c3, h1, l1);
        sts32(hB + rb + i * 8u, h0); sts32(hB + rb + i * 8u + 4u, h1);
        if (lB) { sts32(lB + rb + i * 8u, l0); sts32(lB + rb + i * 8u + 4u, l1); }
    }
    if (nsq_part) *nsq_part = nsq;
}

// 1-mtile fused hi/lo GEMM (HH + HL + LH); warp m-tile = 16 rows
template<int NT>
__device__ __forceinline__ void mma_hl1(float (&acc)[NT][4], u32 aH, u32 aL,
                                        u32 bH, u32 bL, int nk, u32 ap, u32 bp) {
    const int lane = threadIdx.x & 31;
    const u32 aoff = (u32)(lane & 15) * ap + (u32)(lane >> 4) * 16u;
    const u32 boff = (u32)(lane & 15) * bp + (u32)(lane >> 4) * 16u;
    for (int kk = 0; kk < nk; kk++) {
        u32 ah0, ah1, ah2, ah3, al0, al1, al2, al3;
        ldsm4(aH + aoff + (u32)kk * 32u, ah0, ah1, ah2, ah3);
        ldsm4(aL + aoff + (u32)kk * 32u, al0, al1, al2, al3);
#pragma unroll
        for (int ntp = 0; ntp < NT / 2; ntp++) {
            u32 h0, h1, h2, h3, l0, l1, l2, l3;
            ldsm4(bH + boff + (u32)ntp * 16u * bp + (u32)kk * 32u, h0, h1, h2, h3);
            ldsm4(bL + boff + (u32)ntp * 16u * bp + (u32)kk * 32u, l0, l1, l2, l3);
            mma16816(acc[2*ntp],   ah0, ah1, ah2, ah3, h0, h2);
            mma16816(acc[2*ntp],   ah0, ah1, ah2, ah3, l0, l2);
            mma16816(acc[2*ntp],   al0, al1, al2, al3, h0, h2);
            mma16816(acc[2*ntp+1], ah0, ah1, ah2, ah3, h1, h3);
            mma16816(acc[2*ntp+1], ah0, ah1, ah2, ah3, l1, l3);
            mma16816(acc[2*ntp+1], al0, al1, al2, al3, h1, h3);
        }
    }
}

// ---------------- micro init: reset barrier only -------------------------------
__global__ void bar_reset_kernel() {
    if (threadIdx.x == 0) g_bar = 0u;
}

// ---------------- fused persistent kernel --------------------------------------
#define KV_WH 0u
#define KV_WL 18432u
#define KV_KH 36864u
#define KV_KL 55296u
#define KV_PH 73728u
#define KV_PL 108544u
#define KV_VH 143360u
#define KV_VL 161792u
#define KV_ME 180224u
#define KV_NS 180480u
#define OU_WH 0u
#define OU_WL 36864u
#define OU_QH 73728u
#define OU_QL 92160u
#define OU_KVH 110592u
#define OU_KVL 144384u
#define OU_KS 178176u
#define OU_DE 179200u
#define OU_SC 180992u            /* DEDICATED spill buffer: no overlay with live Q */
#define FUSED_SMEM (OU_SC + 33792u)
#define MEAN_SC KV_PH

__device__ __forceinline__ void gbar(u32 target) {
    __syncthreads();
    __threadfence();
    if (threadIdx.x == 0) {
        atomicAdd(&g_bar, 1u);
        while (atomicAdd(&g_bar, 0u) < target) __nanosleep(64);
    }
    __syncthreads();
}

__device__ __forceinline__ void flush_kva(float (&kva)[9][4], int bh, int wm, int lane) {
    const int b = bh >> 1, F0 = (bh & 1) * 128;
    const int f0 = F0 + wm * 16 + (lane >> 2);
#pragma unroll
    for (int nt = 0; nt < 9; nt++) {
        const int d = nt * 8 + (lane & 3) * 2;
        if (nt < 8) {
            atomicAdd(g_kvT + ((size_t)b * DD + d)     * FF + f0,      kva[nt][0]);
            atomicAdd(g_kvT + ((size_t)b * DD + d + 1) * FF + f0,      kva[nt][1]);
            atomicAdd(g_kvT + ((size_t)b * DD + d)     * FF + f0 + 8,  kva[nt][2]);
            atomicAdd(g_kvT + ((size_t)b * DD + d + 1) * FF + f0 + 8,  kva[nt][3]);
        } else if ((lane & 3) == 0) {
            atomicAdd(g_ksum + b * FF + f0,     kva[nt][0]);
            atomicAdd(g_ksum + b * FF + f0 + 8, kva[nt][2]);
        }
    }
}

__global__ void __launch_bounds__(512, 1)
fused_kernel(const float* __restrict__ q, const float* __restrict__ k,
             const float* __restrict__ v, const float* __restrict__ w,
             float* __restrict__ out) {
    extern __shared__ __align__(16) char sm[];
    const u32 smb = smem_u32(sm);
    const int tid = threadIdx.x, wid = tid >> 5, lane = tid & 31;
    const int wm = wid & 7, wn = wid >> 3;   // 8 m-warps x 2 n/k-warps
    const int c = blockIdx.x;
    const int nsm = gridDim.x;

    // ================= phase 0a: zero scratch =================
    {
        float4* kvT4 = (float4*)g_kvT;
        const float4 z4 = make_float4(0.f, 0.f, 0.f, 0.f);
        for (int i = c * 512 + tid; i < (BB * DD * FF) / 4; i += nsm * 512) kvT4[i] = z4;
        for (int i = c * 512 + tid; i < BB * FF; i += nsm * 512) g_ksum[i] = 0.0f;
        for (int i = c * 512 + tid; i < BB * DD; i += nsm * 512) g_mean[i] = 0.0f;
    }
    gbar((u32)nsm);

    // ================= phase 0b: k mean partials =================
    {
        float* red = (float*)(sm + MEAN_SC);   // [8][64]
        const int d = tid & 63, sub = tid >> 6;
        const int m0 = (c * 256) / nsm, m1 = ((c + 1) * 256) / nsm;
        for (int u = m0; u < m1; u++) {
            const int b = u >> 2, p = u & 3;
            const float* kp = k + (size_t)(b * SS + p * 1024) * DD;
            float s = 0.0f;
            for (int r = sub; r < 1024; r += 8) s += kp[r * DD + d];
            red[sub * DD + d] = s;
            __syncthreads();
            if (tid < DD) {
                float t = 0.0f;
#pragma unroll
                for (int j = 0; j < 8; j++) t += red[j * DD + tid];
                atomicAdd(&g_mean[b * DD + tid], t);
            }
            __syncthreads();
        }
    }
    gbar(2u * (u32)nsm);

    // ================= phase 1: kv =================
    {
        float* meanc = (float*)(sm + KV_ME);
        float* nsqs  = (float*)(sm + KV_NS);
        const int u0 = (c * 2048) / nsm, u1 = ((c + 1) * 2048) / nsm;
        int curBH = -1;
        float kva[9][4];
#pragma unroll
        for (int nt = 0; nt < 9; nt++)
#pragma unroll
            for (int j = 0; j < 4; j++) kva[nt][j] = 0.0f;

        for (int u = u0; u < u1; u++) {
            const int bh = u >> 4, zz = u & 15;
            const int b = bh >> 1, F0 = (bh & 1) * 128;
            if (bh != curBH) {
                if (curBH != -1) {
                    flush_kva(kva, curBH, wm, lane);
#pragma unroll
                    for (int nt = 0; nt < 9; nt++)
#pragma unroll
                        for (int j = 0; j < 4; j++) kva[nt][j] = 0.0f;
                }
                __syncthreads();
                if (tid < DD) meanc[tid] = g_mean[b * DD + tid] * (INV_SIGMA / (float)SS);
                if (tid < 256)   // W half, scaled by LOG2E
                    stage_half(smb + KV_WH, smb + KV_WL,
                               (const float4*)(w + (F0 + (tid >> 1)) * DD), tid >> 1, tid & 1,
                               LOG2E, 0, 0);
                __syncthreads();
                curBH = bh;
            }
            for (int t = 0; t < 2; t++) {
                const int s0 = (zz * 2 + t) * 128;
                if (tid < 256) {       // K rows, split halves, nsq via shfl pair
                    const int r = tid >> 1, h = tid & 1;
                    float nsq;
                    stage_half(smb + KV_KH, smb + KV_KL,
                               (const float4*)(k + (size_t)(b * SS + s0 + r) * DD), r, h,
                               INV_SIGMA, meanc, &nsq);
                    nsq += __shfl_xor_sync(~0u, nsq, 1);
                    if (h == 0) nsqs[r] = 0.5f * LOG2E * nsq;
                } else {               // V rows, split halves + ones cols
                    const int sv = (tid - 256) >> 1, h = tid & 1;
                    stage_half(smb + KV_VH, smb + KV_VL,
                               (const float4*)(v + (size_t)(b * SS + s0 + sv) * DD), sv, h,
                               1.0f, 0, 0);
                    if (h == 1) {
                        const u32 rb = (u32)sv * 144u + 128u;
#pragma unroll
                        for (int j = 0; j < 4; j++) {
                            sts32(smb + KV_VH + rb + 4u * j, 0x3F803F80u);
                            sts32(smb + KV_VL + rb + 4u * j, 0u);
                        }
                    }
                }
                __syncthreads();
                // proj: warp = 16 s-rows (wm) x 64 f (wn); fused 3-pass hi/lo
                {
                    float acc[8][4];
#pragma unroll
                    for (int nt = 0; nt < 8; nt++)
#pragma unroll
                        for (int j = 0; j < 4; j++) acc[nt][j] = 0.0f;
                    mma_hl1<8>(acc, smb + KV_KH + (u32)(wm * 16) * 144u,
                                    smb + KV_KL + (u32)(wm * 16) * 144u,
                                    smb + KV_WH + (u32)(wn * 64) * 144u,
                                    smb + KV_WL + (u32)(wn * 64) * 144u, 4, 144u, 144u);
                    const int r0 = wm * 16 + (lane >> 2);
                    const float n0 = nsqs[r0], n1 = nsqs[r0 + 8];
#pragma unroll
                    for (int nt = 0; nt < 8; nt++) {
                        const int f = wn * 64 + nt * 8 + (lane & 3) * 2;
                        float p00 = ex2f(acc[nt][0] - n0);
                        float p01 = ex2f(acc[nt][1] - n0);
                        float p10 = ex2f(acc[nt][2] - n1);
                        float p11 = ex2f(acc[nt][3] - n1);
                        u32 hi, lo;
                        split2(p00, p01, hi, lo);
                        sts32(smb + KV_PH + (u32)r0 * 272u + 2u * f, hi);
                        sts32(smb + KV_PL + (u32)r0 * 272u + 2u * f, lo);
                        split2(p10, p11, hi, lo);
                        sts32(smb + KV_PH + (u32)(r0 + 8) * 272u + 2u * f, hi);
                        sts32(smb + KV_PL + (u32)(r0 + 8) * 272u + 2u * f, lo);
                    }
                }
                __syncthreads();
                // kv gemm: warp = 16 f-rows (wm) x 64-s k-half (wn); trans loads
                {
                    const u32 aoff = ((u32)(lane & 7) + (u32)((lane >> 4) & 1) * 8u) * 272u +
                                     (u32)((lane >> 3) & 1) * 16u + (u32)(wm * 32) +
                                     (u32)(wn * 64) * 272u;
                    const u32 boff = ((u32)(lane & 7) + (u32)((lane >> 3) & 1) * 8u) * 144u +
                                     (u32)((lane >> 4) & 1) * 16u + (u32)(wn * 64) * 144u;
                    const u32 b2off = ((u32)(lane & 7) + (u32)((lane >> 3) & 1) * 8u) * 144u + 128u +
                                      (u32)(wn * 64) * 144u;
                    const u32 PHb = smb + KV_PH, PLb = smb + KV_PL;
                    const u32 VHb = smb + KV_VH, VLb = smb + KV_VL;
                    for (int kk = 0; kk < 4; kk++) {
                        const u32 ka = (u32)kk * 16u * 272u, kb = (u32)kk * 16u * 144u;
                        u32 ah0, ah1, ah2, ah3, al0, al1, al2, al3;
                        ldsm4t(PHb + aoff + ka, ah0, ah1, ah2, ah3);
                        ldsm4t(PLb + aoff + ka, al0, al1, al2, al3);
#pragma unroll
                        for (int ntp = 0; ntp < 4; ntp++) {
                            u32 h0, h1, h2, h3, l0, l1, l2, l3;
                            ldsm4t(VHb + boff + (u32)ntp * 32u + kb, h0, h1, h2, h3);
                            ldsm4t(VLb + boff + (u32)ntp * 32u + kb, l0, l1, l2, l3);
                            mma16816(kva[2*ntp],   ah0, ah1, ah2, ah3, h0, h1);
                            mma16816(kva[2*ntp],   ah0, ah1, ah2, ah3, l0, l1);
                            mma16816(kva[2*ntp],   al0, al1, al2, al3, h0, h1);
                            mma16816(kva[2*ntp+1], ah0, ah1, ah2, ah3, h2, h3);
                            mma16816(kva[2*ntp+1], ah0, ah1, ah2, ah3, l2, l3);
                            mma16816(kva[2*ntp+1], al0, al1, al2, al3, h2, h3);
                        }
                        u32 o0, o1;
                        ldsm2t(VHb + b2off + kb, o0, o1);
                        mma16816(kva[8], ah0, ah1, ah2, ah3, o0, o1);
                        mma16816(kva[8], al0, al1, al2, al3, o0, o1);
                    }
                }
                __syncthreads();
            }
        }
        if (curBH != -1) flush_kva(kva, curBH, wm, lane);
    }
    gbar(3u * (u32)nsm);

    // ================= phase 2: out =================
    {
        float* ksum_s = (float*)(sm + OU_KS);
        float* dn2    = (float*)(sm + OU_DE);
        float* scr    = (float*)(sm + OU_SC);   // dedicated region
        stage_half(smb + OU_WH, smb + OU_WL, (const float4*)(w + (tid >> 1) * DD),
                   tid >> 1, tid & 1, LOG2E, 0, 0);

        const int u0 = (c * 2048) / nsm, u1 = ((c + 1) * 2048) / nsm;
        int curB = -1;
        const u32 qH = smb + OU_QH + (u32)(wm * 16) * 144u;
        const u32 qL = smb + OU_QL + (u32)(wm * 16) * 144u;
        const u32 bofK = (u32)(lane & 15) * 528u + (u32)(lane >> 4) * 16u;

        for (int u = u0; u < u1; u++) {
            const int b = u >> 5, s0 = (u & 31) * 128;
            __syncthreads();
            if (b != curB) {
                if (tid < 256) {
                    ksum_s[tid] = __ldcg(g_ksum + b * FF + tid);
                } else {
                    const int d = (tid - 256) >> 2, qf = (tid - 256) & 3;
                    const float* src = g_kvT + (size_t)b * DD * FF + d * FF + qf * 64;
                    const u32 rb = (u32)d * 528u + (u32)qf * 128u;
#pragma unroll 8
                    for (int j = 0; j < 32; j++) {
                        u32 hi, lo;
                        split2(__ldcg(src + 2*j), __ldcg(src + 2*j + 1), hi, lo);
                        sts32(smb + OU_KVH + rb + 4u * j, hi);
                        sts32(smb + OU_KVL + rb + 4u * j, lo);
                    }
                }
                curB = b;
            }
            if (tid < 256)
                stage_half(smb + OU_QH, smb + OU_QL,
                           (const float4*)(q + (size_t)(b * SS + s0 + (tid >> 1)) * DD),
                           tid >> 1, tid & 1, INV_SIGMA, 0, 0);
            __syncthreads();

            float dp0 = 0.f, dp1 = 0.f;
            float oacc[8][4];
#pragma unroll
            for (int nt = 0; nt < 8; nt++)
#pragma unroll
                for (int j = 0; j < 4; j++) oacc[nt][j] = 0.0f;

            for (int ch = 0; ch < 4; ch++) {
                float acc[4][4];
#pragma unroll
                for (int nt = 0; nt < 4; nt++)
#pragma unroll
                    for (int j = 0; j < 4; j++) acc[nt][j] = 0.0f;
                mma_hl1<4>(acc, qH, qL, smb + OU_WH + (u32)(ch * 64 + wn * 32) * 144u,
                           smb + OU_WL + (u32)(ch * 64 + wn * 32) * 144u, 4, 144u, 144u);
#pragma unroll
                for (int kk = 0; kk < 2; kk++) {
                    u32 aHf[4], aLf[4];
#pragma unroll
                    for (int h = 0; h < 2; h++) {
                        const int nt = kk * 2 + h;
                        const int fg = ch * 64 + wn * 32 + nt * 8 + (lane & 3) * 2;
                        const float ks0 = ksum_s[fg], ks1 = ksum_s[fg + 1];
                        float p00 = ex2f(acc[nt][0]);
                        float p01 = ex2f(acc[nt][1]);
                        float p10 = ex2f(acc[nt][2]);
                        float p11 = ex2f(acc[nt][3]);
                        dp0 += p00 * ks0 + p01 * ks1;
                        dp1 += p10 * ks0 + p11 * ks1;
                        split2(p00, p01, aHf[2*h],     aLf[2*h]);
                        split2(p10, p11, aHf[2*h + 1], aLf[2*h + 1]);
                    }
                    const u32 kb = (u32)(ch * 128 + wn * 64 + kk * 32);
#pragma unroll
                    for (int ntp = 0; ntp < 4; ntp++) {
                        u32 h0, h1, h2, h3, l0, l1, l2, l3;
                        ldsm4(smb + OU_KVH + bofK + (u32)ntp * 16u * 528u + kb, h0, h1, h2, h3);
                        ldsm4(smb + OU_KVL + bofK + (u32)ntp * 16u * 528u + kb, l0, l1, l2, l3);
                        mma16816(oacc[2*ntp],   aHf[0], aHf[1], aHf[2], aHf[3], h0, h2);
                        mma16816(oacc[2*ntp],   aHf[0], aHf[1], aHf[2], aHf[3], l0, l2);
                        mma16816(oacc[2*ntp],   aLf[0], aLf[1], aLf[2], aLf[3], h0, h2);
                        mma16816(oacc[2*ntp+1], aHf[0], aHf[1], aHf[2], aHf[3], h1, h3);
                        mma16816(oacc[2*ntp+1], aHf[0], aHf[1], aHf[2], aHf[3], l1, l3);
                        mma16816(oacc[2*ntp+1], aLf[0], aLf[1], aLf[2], aLf[3], h1, h3);
                    }
                }
            }
            // deno partials
            dp0 += __shfl_xor_sync(~0u, dp0, 1);
            dp0 += __shfl_xor_sync(~0u, dp0, 2);
            dp1 += __shfl_xor_sync(~0u, dp1, 1);
            dp1 += __shfl_xor_sync(~0u, dp1, 2);
            const int r0 = wm * 16 + (lane >> 2);
            if ((lane & 3) == 0) {
                dn2[wn * 128 + r0]     = dp0;
                dn2[wn * 128 + r0 + 8] = dp1;
            }
            if (wn == 1) {
#pragma unroll
                for (int nt = 0; nt < 8; nt++) {
                    const int d = nt * 8 + (lane & 3) * 2;
                    *(float2*)(scr + r0 * 66 + d)       = make_float2(oacc[nt][0], oacc[nt][1]);
                    *(float2*)(scr + (r0 + 8) * 66 + d) = make_float2(oacc[nt][2], oacc[nt][3]);
                }
            }
            __syncthreads();
            if (wn == 0) {
                const float i0 = 1.0f / fmaxf(dn2[r0] + dn2[128 + r0], 1e-4f);
                const float i1 = 1.0f / fmaxf(dn2[r0 + 8] + dn2[128 + r0 + 8], 1e-4f);
#pragma unroll
                for (int nt = 0; nt < 8; nt++) {
                    const int d = nt * 8 + (lane & 3) * 2;
                    float2 s0v = *(const float2*)(scr + r0 * 66 + d);
                    float2 s1v = *(const float2*)(scr + (r0 + 8) * 66 + d);
                    *(float2*)(out + (size_t)(b * SS + s0 + r0) * DD + d) =
                        make_float2((oacc[nt][0] + s0v.x) * i0, (oacc[nt][1] + s0v.y) * i0);
                    *(float2*)(out + (size_t)(b * SS + s0 + r0 + 8) * DD + d) =
                        make_float2((oacc[nt][2] + s1v.x) * i1, (oacc[nt][3] + s1v.y) * i1);
                }
            }
        }
    }
}

// ---------------- launch ------------------------------------------------------
extern "C" void kernel_launch(void* const* d_in, const int* in_sizes, int n_in,
                              void* d_out, int out_size) {
    const float* q = (const float*)d_in[0];
    const float* k = (const float*)d_in[1];
    const float* v = (const float*)d_in[2];
    const float* w = (const float*)d_in[3];
    float* out = (float*)d_out;
    int nsm = 148, dev = 0;
    cudaGetDevice(&dev);
    cudaDeviceGetAttribute(&nsm, cudaDevAttrMultiProcessorCount, dev);
    cudaFuncSetAttribute(fused_kernel, cudaFuncAttributeMaxDynamicSharedMemorySize, FUSED_SMEM);
    bar_reset_kernel<<<1, 32>>>();
    fused_kernel<<<nsm, 512, FUSED_SMEM>>>(q, k, v, w, out);
}